// round 1
// baseline (speedup 1.0000x reference)
#include <cuda_runtime.h>

#define NN   50000
#define NE   1600000
#define NR   8
#define KC   1152        // NR*128 + 128 (relation means ++ self term)
#define CAP  16384       // max compacted "needed" nodes (expected ~8.4K)
#define NP   256
#define DOUT 64

// ---- scratch (device globals: no allocation allowed in kernel_launch) ----
__device__ int   g_pmap[NN];          // node is a pooled dst
__device__ int   g_nf[NN];            // node is "needed" (pool or src-of-edge-into-pool)
__device__ int   g_cid[NN];           // node -> compact id
__device__ int   g_nodes[CAP];        // compact id -> node
__device__ int   g_counter;           // number of needed nodes
__device__ int   g_head[NR * NN];     // per (rel,dst) linked-list head (edge index), -1 = empty
__device__ int   g_next[NE];          // linked-list next (indexed by edge id)
__device__ float g_C[(size_t)CAP * KC];   // per needed node: [mean_r0..mean_r7, x[v]] (1152)
__device__ float g_h[(size_t)CAP * 128];  // layer-1 output at needed nodes
__device__ float g_part[NP * DOUT];       // per-pool-slot weighted layer-2 output
__device__ float g_wp[NP];                // per-pool-slot entity weight

// ---------------------------------------------------------------- init
__global__ void k_init() {
    int i = blockIdx.x * blockDim.x + threadIdx.x;
    if (i < NR * NN) g_head[i] = -1;
    if (i < NN) { g_pmap[i] = 0; g_nf[i] = 0; }
    if (i == 0) g_counter = 0;
}

__global__ void k_mark_pool(const int* __restrict__ pool) {
    int p = pool[threadIdx.x];
    g_pmap[p] = 1;
    g_nf[p]   = 1;
}

// mark sources of edges whose dst is pooled (those need h)
__global__ void k_mark_src(const int* __restrict__ ei) {
    int e = blockIdx.x * blockDim.x + threadIdx.x;
    if (e >= NE) return;
    int dst = ei[NE + e];
    if (g_pmap[dst]) g_nf[ei[e]] = 1;
}

__global__ void k_compact() {
    int v = blockIdx.x * blockDim.x + threadIdx.x;
    if (v >= NN) return;
    if (g_nf[v]) {
        int c = atomicAdd(&g_counter, 1);
        if (c < CAP) { g_cid[v] = c; g_nodes[c] = v; }
    }
}

// build per-(rel,dst) linked lists over relevant edges only (dst needed).
// slot id == edge id (unique), so no append counter and src comes from ei[ptr].
__global__ void k_build(const int* __restrict__ ei, const int* __restrict__ et) {
    int e = blockIdx.x * blockDim.x + threadIdx.x;
    if (e >= NE) return;
    int dst = ei[NE + e];
    if (!g_nf[dst]) return;
    int r = et[e];
    g_next[e] = atomicExch(&g_head[r * NN + dst], e);
}

// ------------------------------------------------- layer-1 aggregation
// task = (compact node i, r in 0..8). r<8: mean of x[src] over segment.
// r==8: copy x[v] (self/root chunk). One warp per task, float4 per lane.
__global__ void k_agg1(const float* __restrict__ x, const int* __restrict__ ei) {
    const float4* x4 = (const float4*)x;
    int wid   = (blockIdx.x * blockDim.x + threadIdx.x) >> 5;
    int lane  = threadIdx.x & 31;
    int nwarp = (gridDim.x * blockDim.x) >> 5;
    int cnt   = min(g_counter, CAP);
    int ntask = cnt * 9;
    for (int t = wid; t < ntask; t += nwarp) {
        int i = t / 9;
        int r = t - i * 9;
        int v = g_nodes[i];
        float4 acc = make_float4(0.f, 0.f, 0.f, 0.f);
        if (r == 8) {
            acc = x4[v * 32 + lane];
        } else {
            int ptr = g_head[r * NN + v];
            int c = 0;
            while (ptr >= 0) {
                int src = ei[ptr];
                float4 xv = x4[src * 32 + lane];
                acc.x += xv.x; acc.y += xv.y; acc.z += xv.z; acc.w += xv.w;
                c++;
                ptr = g_next[ptr];
            }
            if (c > 1) {
                float s = 1.0f / (float)c;
                acc.x *= s; acc.y *= s; acc.z *= s; acc.w *= s;
            }
        }
        *(float4*)&g_C[(size_t)i * KC + r * 128 + lane * 4] = acc;
    }
}

// ------------------------------------------------- layer-1 GEMM + relu
// h[i][:] = relu(C[i][:] @ [W1; root1] + b1),  M = n_needed, N = 128, K = 1152
// Tile: 32 rows x 128 cols per block, 256 threads, 4x4 microtile/thread.
__global__ void __launch_bounds__(256) k_gemm1(const float* __restrict__ W1,
                                               const float* __restrict__ root1,
                                               const float* __restrict__ b1) {
    __shared__ float Cs[64 * 36];    // [k][row], pad 36 (float4-aligned row groups)
    __shared__ float Ws[64 * 128];   // [k][col]
    int cnt  = min(g_counter, CAP);
    int row0 = blockIdx.x * 32;
    if (row0 >= cnt) return;
    int t  = threadIdx.x;
    int cg = t & 31;   // col group: cols cg*4..cg*4+3
    int rg = t >> 5;   // row group: rows rg*4..rg*4+3

    float acc[4][4];
#pragma unroll
    for (int i = 0; i < 4; i++)
#pragma unroll
        for (int j = 0; j < 4; j++) acc[i][j] = 0.f;

    for (int kc = 0; kc < KC / 64; kc++) {
        // stage C tile (32 rows x 64 k), transposed into Cs[k][row]
#pragma unroll
        for (int q = 0; q < 8; q++) {
            int idx = t + q * 256;
            int row = idx >> 6, k = idx & 63;
            int gr = row0 + row;
            float v = (gr < cnt) ? g_C[(size_t)gr * KC + kc * 64 + k] : 0.f;
            Cs[k * 36 + row] = v;
        }
        // stage W slab (64 k x 128 cols); k<1024 -> W1 flat, else root1
#pragma unroll
        for (int q = 0; q < 8; q++) {
            int idx = t + q * 256;          // float4 index
            int k = idx >> 5, c4 = idx & 31;
            int gk = kc * 64 + k;
            float4 wv = (gk < 1024) ? *(const float4*)&W1[gk * 128 + c4 * 4]
                                    : *(const float4*)&root1[(gk - 1024) * 128 + c4 * 4];
            *(float4*)&Ws[k * 128 + c4 * 4] = wv;
        }
        __syncthreads();
#pragma unroll 16
        for (int k = 0; k < 64; k++) {
            float4 b4 = *(const float4*)&Ws[k * 128 + cg * 4];
            float4 a4 = *(const float4*)&Cs[k * 36 + rg * 4];
            float a_[4] = {a4.x, a4.y, a4.z, a4.w};
            float b_[4] = {b4.x, b4.y, b4.z, b4.w};
#pragma unroll
            for (int i = 0; i < 4; i++)
#pragma unroll
                for (int j = 0; j < 4; j++) acc[i][j] += a_[i] * b_[j];
        }
        __syncthreads();
    }

    float4 bb = *(const float4*)&b1[cg * 4];
    float bv[4] = {bb.x, bb.y, bb.z, bb.w};
#pragma unroll
    for (int i = 0; i < 4; i++) {
        int gr = row0 + rg * 4 + i;
        if (gr < cnt) {
            float4 o;
            o.x = fmaxf(acc[i][0] + bv[0], 0.f);
            o.y = fmaxf(acc[i][1] + bv[1], 0.f);
            o.z = fmaxf(acc[i][2] + bv[2], 0.f);
            o.w = fmaxf(acc[i][3] + bv[3], 0.f);
            *(float4*)&g_h[(size_t)gr * 128 + cg * 4] = o;
        }
    }
}

// -------------------------------- layer-2 (256 pooled rows) + weighting
// One block per pool slot: aggregate 8 relation means of h + self term into
// smem C row (1152), then matvec with [W2; root2] (N=64), apply entity weight.
__global__ void __launch_bounds__(256) k_pool(const float* __restrict__ x,
                                              const int* __restrict__ pool,
                                              const int* __restrict__ ei,
                                              const float* __restrict__ W2,
                                              const float* __restrict__ root2,
                                              const float* __restrict__ b2) {
    __shared__ float cs[KC];
    __shared__ float red[256];
    const float4* h4 = (const float4*)g_h;
    int p = pool[blockIdx.x];
    int t = threadIdx.x;
    int lane = t & 31, w = t >> 5;   // 8 warps == 8 relations

    {
        int r = w;
        int ptr = g_head[r * NN + p];
        int c = 0;
        float4 acc = make_float4(0.f, 0.f, 0.f, 0.f);
        while (ptr >= 0) {
            int src = ei[ptr];
            int ci = g_cid[src];
            float4 hv = h4[ci * 32 + lane];
            acc.x += hv.x; acc.y += hv.y; acc.z += hv.z; acc.w += hv.w;
            c++;
            ptr = g_next[ptr];
        }
        if (c > 1) {
            float s = 1.0f / (float)c;
            acc.x *= s; acc.y *= s; acc.z *= s; acc.w *= s;
        }
        *(float4*)&cs[r * 128 + lane * 4] = acc;
    }
    if (t < 128) {
        int cp = g_cid[p];
        cs[1024 + t] = g_h[(size_t)cp * 128 + t];
    }
    __syncthreads();

    int j = t & 63, q = t >> 6;   // 4-way K split
    float s = 0.f;
    int k0 = q * 288;
#pragma unroll 4
    for (int k = k0; k < k0 + 288; k++) {
        float wv = (k < 1024) ? W2[k * 64 + j] : root2[(k - 1024) * 64 + j];
        s += cs[k] * wv;
    }
    red[t] = s;
    __syncthreads();
    if (t < 64) {
        float o = red[t] + red[t + 64] + red[t + 128] + red[t + 192] + b2[j];
        float wp = 4.f * x[p * 128 + 0] + x[p * 128 + 1] + 2.f * x[p * 128 + 2];
        g_part[blockIdx.x * 64 + j] = o * wp;
        if (j == 0) g_wp[blockIdx.x] = wp;
    }
}

// fixed-order final reduction (deterministic)
__global__ void k_final(float* __restrict__ out) {
    int j = threadIdx.x;   // 64
    float acc = 0.f;
    for (int i = 0; i < NP; i++) acc += g_part[i * 64 + j];
    float ws = 0.f;
    for (int i = 0; i < NP; i++) ws += g_wp[i];
    out[j] = acc / (ws + 1e-9f);
}

// ---------------------------------------------------------------- launch
extern "C" void kernel_launch(void* const* d_in, const int* in_sizes, int n_in,
                              void* d_out, int out_size) {
    const float* x     = (const float*)d_in[0];
    const int*   ei    = (const int*)  d_in[1];   // [2, NE]: src row 0, dst row 1
    const int*   et    = (const int*)  d_in[2];
    const int*   pool  = (const int*)  d_in[3];
    const float* W1    = (const float*)d_in[4];
    const float* root1 = (const float*)d_in[5];
    const float* b1    = (const float*)d_in[6];
    const float* W2    = (const float*)d_in[7];
    const float* root2 = (const float*)d_in[8];
    const float* b2    = (const float*)d_in[9];
    float* out = (float*)d_out;
    (void)in_sizes; (void)n_in; (void)out_size;

    k_init     <<<(NR * NN + 255) / 256, 256>>>();
    k_mark_pool<<<1, NP>>>(pool);
    k_mark_src <<<(NE + 255) / 256, 256>>>(ei);
    k_compact  <<<(NN + 255) / 256, 256>>>();
    k_build    <<<(NE + 255) / 256, 256>>>(ei, et);
    k_agg1     <<<1024, 256>>>(x, ei);
    k_gemm1    <<<CAP / 32, 256>>>(W1, root1, b1);
    k_pool     <<<NP, 256>>>(x, pool, ei, W2, root2, b2);
    k_final    <<<1, 64>>>(out);
}